// round 7
// baseline (speedup 1.0000x reference)
#include <cuda_runtime.h>
#include <cstdint>

#define NEGV (-999999.0f)

constexpr int B = 2, H = 16, L = 2048, D = 64;
constexpr int BQ = 128, BK = 64;
constexpr int PW = 72;                // smem row stride (floats), conflict-free LDS.64
constexpr int THREADS = 256;          // 8 warps, each owns m16 of the 128-row q tile

// scratch (pre-converted tf32, mma-friendly layouts)
__device__ float g_Kc[B * H * L * D];   // [bh][key][d']   d interleaved within 8-groups
__device__ float g_Vt[B * H * D * L];   // [bh][d][key']   transposed, key interleaved
__device__ float g_vmean[B * H * D];

__device__ __forceinline__ int perm8(int k) { return 2 * (k & 3) + ((k >> 2) & 1); }
__device__ __forceinline__ int iperm8(int c) { return ((c & 1) << 2) + (c >> 1); }

__device__ __forceinline__ uint32_t tf32r(float f) {
    uint32_t u; asm("cvt.rna.tf32.f32 %0, %1;" : "=r"(u) : "f"(f)); return u;
}
__device__ __forceinline__ float tf32f(float f) { return __uint_as_float(tf32r(f)); }
__device__ __forceinline__ uint32_t fau(float f) { return __float_as_uint(f); }

__device__ __forceinline__ void mma8(float* c, uint32_t a0, uint32_t a1, uint32_t a2, uint32_t a3,
                                     uint32_t b0, uint32_t b1) {
    asm volatile(
        "mma.sync.aligned.m16n8k8.row.col.f32.tf32.tf32.f32 "
        "{%0,%1,%2,%3},{%4,%5,%6,%7},{%8,%9},{%0,%1,%2,%3};"
        : "+f"(c[0]), "+f"(c[1]), "+f"(c[2]), "+f"(c[3])
        : "r"(a0), "r"(a1), "r"(a2), "r"(a3), "r"(b0), "r"(b1));
}

__device__ __forceinline__ void cp_async16(uint32_t saddr, const void* g) {
    asm volatile("cp.async.cg.shared.global [%0], [%1], 16;" :: "r"(saddr), "l"(g));
}

// ---------------------------------------------------------------------------
// Pre-pass kernels
// ---------------------------------------------------------------------------
__global__ void kprep_kernel(const float* __restrict__ K) {
    int idx = blockIdx.x * 256 + threadIdx.x;          // over B*H*L*D
    float v = K[idx];
    int d = idx & 63;
    int dst = (idx & ~63) | (d & ~7) | perm8(d & 7);
    g_Kc[dst] = tf32f(v);
}

__global__ void vtrans_kernel(const float* __restrict__ V) {
    // grid (L/64, B*H); 64key x 64d tile transpose with key-interleave
    __shared__ float t[64][65];
    int k0 = blockIdx.x * 64;
    int bh = blockIdx.y;
    const float* vp = V + ((size_t)bh * L + k0) * D;
    int tid = threadIdx.x;
#pragma unroll
    for (int i = 0; i < 16; ++i) {
        int e = i * 256 + tid;
        t[e >> 6][e & 63] = vp[e];
    }
    __syncthreads();
    float* op = g_Vt + (size_t)bh * D * L + k0;
#pragma unroll
    for (int i = 0; i < 16; ++i) {
        int e = i * 256 + tid;
        int d = e >> 6, c = e & 63;                    // c = key' within tile
        int key = (c & ~7) | iperm8(c & 7);
        op[(size_t)d * L + c] = tf32f(t[key][d]);
    }
}

__global__ void vmean_kernel(const float* __restrict__ V) {
    int bh = blockIdx.x;
    int d  = threadIdx.x & 63;
    int c  = threadIdx.x >> 6;
    __shared__ float part[4][64];
    const float* vp = V + (size_t)bh * L * D;
    float s = 0.f;
    for (int k = c * 512; k < c * 512 + 512; ++k) s += vp[(size_t)k * D + d];
    part[c][d] = s;
    __syncthreads();
    if (c == 0)
        g_vmean[bh * D + d] = (part[0][d] + part[1][d] + part[2][d] + part[3][d]) * (1.0f / 2048.0f);
}

// ---------------------------------------------------------------------------
// Main attention kernel: 128-row q tiles, 8 warps, double-buffered 64-key tiles
// ---------------------------------------------------------------------------
__global__ __launch_bounds__(THREADS)
void attn_kernel(const float* __restrict__ Q, const int* __restrict__ qmask,
                 const int* __restrict__ vmask, const float* __restrict__ bias,
                 float* __restrict__ out) {
    extern __shared__ float smem[];
    float* Qs = smem;                        // [128][PW] interleaved d
    float* Ps = Qs + BQ * PW;                // [128][PW] interleaved key
    float* Ks[2] = { Ps + BQ * PW, Ps + BQ * PW + BK * PW };     // [64][PW]
    float* Vs[2] = { Ks[1] + BK * PW, Ks[1] + 2 * BK * PW };     // [64][PW]

    const int qt = blockIdx.x;
    const int bh = blockIdx.y;
    const int q0 = qt * BQ;

    const float* Qg = Q + ((size_t)bh * L + q0) * D;
    const float* Kg = g_Kc + (size_t)bh * L * D;
    const float* Vg = g_Vt + (size_t)bh * D * L;
    const float* Bg = bias + ((size_t)bh * L + q0) * L;
    const int*  vmg = vmask + (size_t)bh * L;

    const int tid = threadIdx.x;
    const int w = tid >> 5, lane = tid & 31;
    const int g = lane >> 2, tig = lane & 3;

    const uint32_t sKs[2] = { (uint32_t)__cvta_generic_to_shared(Ks[0]),
                              (uint32_t)__cvta_generic_to_shared(Ks[1]) };
    const uint32_t sVs[2] = { (uint32_t)__cvta_generic_to_shared(Vs[0]),
                              (uint32_t)__cvta_generic_to_shared(Vs[1]) };

    const int nkt = (q0 + BQ) / BK;          // causal tile count: 2*qt+2

    // prefetch tile 0 (buf 0): 64x64 tile = 1024 chunks -> 4 chunks/thread/array
    {
#pragma unroll
        for (int i = 0; i < 4; ++i) {
            int c = tid + i * 256;
            int r = c >> 4, sg = (c & 15) * 4;
            cp_async16(sKs[0] + (r * PW + sg) * 4, Kg + r * 64 + sg);
            cp_async16(sVs[0] + (r * PW + sg) * 4, Vg + (size_t)r * L + sg);
        }
        asm volatile("cp.async.commit_group;");
    }

    // stage Q (scaled, tf32, d-interleaved): BQ*D = 8192 floats
    for (int idx = tid * 4; idx < BQ * D; idx += THREADS * 4) {
        float4 v = *(const float4*)(Qg + idx);
        int r = idx >> 6, c = idx & 63;
        float* p = Qs + r * PW + (c & ~7);
        int half = (c >> 2) & 1;
        p[half + 0] = tf32f(v.x * 0.125f);
        p[half + 2] = tf32f(v.y * 0.125f);
        p[half + 4] = tf32f(v.z * 0.125f);
        p[half + 6] = tf32f(v.w * 0.125f);
    }

    float o[8][4];
    float m0 = -1e30f, m1 = -1e30f, l0 = 0.f, l1 = 0.f;
#pragma unroll
    for (int j = 0; j < 8; ++j) { o[j][0] = o[j][1] = o[j][2] = o[j][3] = 0.f; }

    const int row0 = 16 * w + g;
    const int gq0 = q0 + row0, gq1 = gq0 + 8;
    const int pofs0 = ((tig & 1) << 2) + (tig >> 1);   // Ps store offsets (interleaved)
    const int pofs1 = pofs0 + 2;

    for (int kt = 0; kt < nkt; ++kt) {
        const int k0 = kt * BK;
        const int buf = kt & 1;
        asm volatile("cp.async.wait_group 0;");
        __syncthreads();

        // prefetch next tile into other buffer
        if (kt + 1 < nkt) {
            const int nk0 = (kt + 1) * BK;
            const int nb = buf ^ 1;
#pragma unroll
            for (int i = 0; i < 4; ++i) {
                int c = tid + i * 256;
                int r = c >> 4, sg = (c & 15) * 4;
                cp_async16(sKs[nb] + (r * PW + sg) * 4, Kg + (size_t)(nk0 + r) * 64 + sg);
                cp_async16(sVs[nb] + (r * PW + sg) * 4, Vg + (size_t)r * L + nk0 + sg);
            }
            asm volatile("cp.async.commit_group;");
        }

        // bias + mask prefetch (in flight during S-mma)
        float2 bv0[8], bv1[8]; int2 vmk[8];
#pragma unroll
        for (int j = 0; j < 8; ++j) {
            int c0 = k0 + 8 * j + 2 * tig;
            bv0[j] = *(const float2*)(Bg + (size_t)row0 * L + c0);
            bv1[j] = *(const float2*)(Bg + (size_t)(row0 + 8) * L + c0);
            vmk[j] = *(const int2*)(vmg + c0);
        }

        // ---- S = Q K^T ----
        float s[8][4];
#pragma unroll
        for (int j = 0; j < 8; ++j) { s[j][0] = s[j][1] = s[j][2] = s[j][3] = 0.f; }
        const float* Kb = Ks[buf];
#pragma unroll
        for (int kk = 0; kk < 8; ++kk) {
            int co = 8 * kk + 2 * tig;
            float2 aA = *(const float2*)(Qs + row0 * PW + co);        // (a0, a2)
            float2 aB = *(const float2*)(Qs + (row0 + 8) * PW + co);  // (a1, a3)
#pragma unroll
            for (int j = 0; j < 8; ++j) {
                float2 b = *(const float2*)(Kb + (8 * j + g) * PW + co);
                mma8(s[j], fau(aA.x), fau(aB.x), fau(aA.y), fau(aB.y), fau(b.x), fau(b.y));
            }
        }

        // ---- bias + mask ----
#pragma unroll
        for (int j = 0; j < 8; ++j) {
            int c0 = k0 + 8 * j + 2 * tig;
            bool mk0 = vmk[j].x != 0, mk1 = vmk[j].y != 0;
            s[j][0] = (mk0 && c0     <= gq0) ? s[j][0] + bv0[j].x : NEGV;
            s[j][1] = (mk1 && c0 + 1 <= gq0) ? s[j][1] + bv0[j].y : NEGV;
            s[j][2] = (mk0 && c0     <= gq1) ? s[j][2] + bv1[j].x : NEGV;
            s[j][3] = (mk1 && c0 + 1 <= gq1) ? s[j][3] + bv1[j].y : NEGV;
        }

        // ---- online softmax ----
        float tm0 = -1e30f, tm1 = -1e30f;
#pragma unroll
        for (int j = 0; j < 8; ++j) {
            tm0 = fmaxf(tm0, fmaxf(s[j][0], s[j][1]));
            tm1 = fmaxf(tm1, fmaxf(s[j][2], s[j][3]));
        }
        tm0 = fmaxf(tm0, __shfl_xor_sync(0xffffffffu, tm0, 1));
        tm0 = fmaxf(tm0, __shfl_xor_sync(0xffffffffu, tm0, 2));
        tm1 = fmaxf(tm1, __shfl_xor_sync(0xffffffffu, tm1, 1));
        tm1 = fmaxf(tm1, __shfl_xor_sync(0xffffffffu, tm1, 2));
        float nm0 = fmaxf(m0, tm0), nm1 = fmaxf(m1, tm1);
        float al0 = __expf(m0 - nm0), al1 = __expf(m1 - nm1);
        m0 = nm0; m1 = nm1;
        float sum0 = 0.f, sum1 = 0.f;
#pragma unroll
        for (int j = 0; j < 8; ++j) {
            s[j][0] = __expf(s[j][0] - m0); sum0 += s[j][0];
            s[j][1] = __expf(s[j][1] - m0); sum0 += s[j][1];
            s[j][2] = __expf(s[j][2] - m1); sum1 += s[j][2];
            s[j][3] = __expf(s[j][3] - m1); sum1 += s[j][3];
        }
        sum0 += __shfl_xor_sync(0xffffffffu, sum0, 1);
        sum0 += __shfl_xor_sync(0xffffffffu, sum0, 2);
        sum1 += __shfl_xor_sync(0xffffffffu, sum1, 1);
        sum1 += __shfl_xor_sync(0xffffffffu, sum1, 2);
        l0 = l0 * al0 + sum0;
        l1 = l1 * al1 + sum1;
#pragma unroll
        for (int j = 0; j < 8; ++j) {
            o[j][0] *= al0; o[j][1] *= al0; o[j][2] *= al1; o[j][3] *= al1;
            float* pr0 = Ps + row0 * PW + 8 * j;
            float* pr1 = Ps + (row0 + 8) * PW + 8 * j;
            pr0[pofs0] = tf32f(s[j][0]);
            pr0[pofs1] = tf32f(s[j][1]);
            pr1[pofs0] = tf32f(s[j][2]);
            pr1[pofs1] = tf32f(s[j][3]);
        }
        __syncwarp();

        // ---- O += P V ----
        const float* Vb = Vs[buf];
#pragma unroll
        for (int kk = 0; kk < 8; ++kk) {
            int co = 8 * kk + 2 * tig;
            float2 aA = *(const float2*)(Ps + row0 * PW + co);
            float2 aB = *(const float2*)(Ps + (row0 + 8) * PW + co);
#pragma unroll
            for (int j = 0; j < 8; ++j) {
                float2 b = *(const float2*)(Vb + (8 * j + g) * PW + co);
                mma8(o[j], fau(aA.x), fau(aB.x), fau(aA.y), fau(aB.y), fau(b.x), fau(b.y));
            }
        }
        __syncwarp();   // protect Ps before next iteration's rewrite
    }

    // ---- epilogue ----
    int qm0 = qmask[(size_t)bh * L + gq0];
    int qm1 = qmask[(size_t)bh * L + gq1];
    bool fm0 = (m0 < -1e5f), fm1 = (m1 < -1e5f);
    float il0 = 1.0f / l0, il1 = 1.0f / l1;
#pragma unroll
    for (int j = 0; j < 8; ++j) {
        int c = 8 * j + 2 * tig;
        float2 r0, r1;
        r0.x = !qm0 ? 0.f : (fm0 ? g_vmean[bh * D + c]     : o[j][0] * il0);
        r0.y = !qm0 ? 0.f : (fm0 ? g_vmean[bh * D + c + 1] : o[j][1] * il0);
        r1.x = !qm1 ? 0.f : (fm1 ? g_vmean[bh * D + c]     : o[j][2] * il1);
        r1.y = !qm1 ? 0.f : (fm1 ? g_vmean[bh * D + c + 1] : o[j][3] * il1);
        *(float2*)(out + ((size_t)bh * L + gq0) * D + c) = r0;
        *(float2*)(out + ((size_t)bh * L + gq1) * D + c) = r1;
    }
}

// ---------------------------------------------------------------------------
extern "C" void kernel_launch(void* const* d_in, const int* in_sizes, int n_in,
                              void* d_out, int out_size) {
    const float* Q  = (const float*)d_in[0];
    const float* K  = (const float*)d_in[1];
    const float* V  = (const float*)d_in[2];
    const int* qm   = (const int*)d_in[3];
    const int* vm   = (const int*)d_in[4];
    const float* bi = (const float*)d_in[5];
    float* out = (float*)d_out;

    constexpr int SMEM_BYTES = (2 * BQ + 4 * BK) * PW * (int)sizeof(float);  // 144 KB
    cudaFuncSetAttribute(attn_kernel, cudaFuncAttributeMaxDynamicSharedMemorySize, SMEM_BYTES);

    kprep_kernel<<<(B * H * L * D) / 256, 256>>>(K);
    vtrans_kernel<<<dim3(L / 64, B * H), 256>>>(V);
    vmean_kernel<<<B * H, 256>>>(V);
    attn_kernel<<<dim3(L / BQ, B * H), THREADS, SMEM_BYTES>>>(Q, qm, vm, bi, out);
}

// round 10
// speedup vs baseline: 1.2784x; 1.2784x over previous
#include <cuda_runtime.h>
#include <cstdint>

constexpr int B = 2, H = 16, L = 2048, D = 64;
constexpr int BQ = 64, BK = 64;
constexpr int PW = 72;                // smem row stride (floats), conflict-free LDS.64
constexpr int THREADS = 128;
constexpr int NQT = L / BQ;           // 32

// scratch (pre-converted tf32, mma-friendly interleaved layouts)
__device__ float g_Kc[B * H * L * D];   // [bh][key][d']   d interleaved within 8-groups
__device__ float g_Vt[B * H * D * L];   // [bh][d][key']   transposed, key interleaved
__device__ float g_vmean[B * H * D];

__device__ __forceinline__ int perm8(int k) { return 2 * (k & 3) + ((k >> 2) & 1); }
__device__ __forceinline__ int iperm8(int c) { return ((c & 1) << 2) + (c >> 1); }

__device__ __forceinline__ uint32_t tf32r(float f) {
    uint32_t u; asm("cvt.rna.tf32.f32 %0, %1;" : "=r"(u) : "f"(f)); return u;
}
__device__ __forceinline__ float tf32f(float f) { return __uint_as_float(tf32r(f)); }
__device__ __forceinline__ uint32_t fau(float f) { return __float_as_uint(f); }

__device__ __forceinline__ void mma8(float* c, uint32_t a0, uint32_t a1, uint32_t a2, uint32_t a3,
                                     uint32_t b0, uint32_t b1) {
    asm volatile(
        "mma.sync.aligned.m16n8k8.row.col.f32.tf32.tf32.f32 "
        "{%0,%1,%2,%3},{%4,%5,%6,%7},{%8,%9},{%0,%1,%2,%3};"
        : "+f"(c[0]), "+f"(c[1]), "+f"(c[2]), "+f"(c[3])
        : "r"(a0), "r"(a1), "r"(a2), "r"(a3), "r"(b0), "r"(b1));
}

__device__ __forceinline__ void cp_async16(uint32_t saddr, const void* g) {
    asm volatile("cp.async.cg.shared.global [%0], [%1], 16;" :: "r"(saddr), "l"(g));
}

// ---------------------------------------------------------------------------
// Pre-pass kernels
// ---------------------------------------------------------------------------
__global__ void kprep_kernel(const float* __restrict__ K) {
    int idx = blockIdx.x * 256 + threadIdx.x;
    float v = K[idx];
    int d = idx & 63;
    int dst = (idx & ~63) | (d & ~7) | perm8(d & 7);
    g_Kc[dst] = tf32f(v);
}

__global__ void vtrans_kernel(const float* __restrict__ V) {
    __shared__ float t[64][65];
    int k0 = blockIdx.x * 64;
    int bh = blockIdx.y;
    const float* vp = V + ((size_t)bh * L + k0) * D;
    int tid = threadIdx.x;
#pragma unroll
    for (int i = 0; i < 16; ++i) {
        int e = i * 256 + tid;
        t[e >> 6][e & 63] = vp[e];
    }
    __syncthreads();
    float* op = g_Vt + (size_t)bh * D * L + k0;
#pragma unroll
    for (int i = 0; i < 16; ++i) {
        int e = i * 256 + tid;
        int d = e >> 6, c = e & 63;
        int key = (c & ~7) | iperm8(c & 7);
        op[(size_t)d * L + c] = tf32f(t[key][d]);
    }
}

__global__ void vmean_kernel(const float* __restrict__ V) {
    int bh = blockIdx.x;
    int d = threadIdx.x & 63;
    int c = threadIdx.x >> 6;
    __shared__ float part[4][64];
    const float* vp = V + (size_t)bh * L * D;
    float s = 0.f;
    for (int k = c * 512; k < c * 512 + 512; ++k) s += vp[(size_t)k * D + d];
    part[c][d] = s;
    __syncthreads();
    if (c == 0)
        g_vmean[bh * D + d] = (part[0][d] + part[1][d] + part[2][d] + part[3][d]) * (1.0f / 2048.0f);
}

// ---------------------------------------------------------------------------
// Main attention kernel: 4 warps, Q/P in registers, no-max softmax,
// double-buffered K/V, 3 CTAs/SM
// ---------------------------------------------------------------------------
__global__ __launch_bounds__(THREADS, 3)
void attn_kernel(const float* __restrict__ Q, const int* __restrict__ qmask,
                 const int* __restrict__ vmask, const float* __restrict__ bias,
                 float* __restrict__ out) {
    extern __shared__ float smem[];
    float* Ks[2] = { smem, smem + BK * PW };
    float* Vs[2] = { smem + 2 * BK * PW, smem + 3 * BK * PW };

    const int qt = (NQT - 1) - blockIdx.x;        // big tiles first
    const int bh = blockIdx.y;
    const int q0 = qt * BQ;

    const float* Qg = Q + ((size_t)bh * L + q0) * D;
    const float* Kg = g_Kc + (size_t)bh * L * D;
    const float* Vg = g_Vt + (size_t)bh * D * L;
    const float* Bg = bias + ((size_t)bh * L + q0) * L;
    const int*  vmg = vmask + (size_t)bh * L;

    const int tid = threadIdx.x;
    const int w = tid >> 5, lane = tid & 31;
    const int g = lane >> 2, tig = lane & 3;

    const uint32_t sKs[2] = { (uint32_t)__cvta_generic_to_shared(Ks[0]),
                              (uint32_t)__cvta_generic_to_shared(Ks[1]) };
    const uint32_t sVs[2] = { (uint32_t)__cvta_generic_to_shared(Vs[0]),
                              (uint32_t)__cvta_generic_to_shared(Vs[1]) };

    const int nkt = qt + 1;

    // prefetch tile 0: 64x64 floats = 1024 16B-chunks -> 8/thread/array
    {
#pragma unroll
        for (int i = 0; i < 8; ++i) {
            int c = tid + i * 128;
            int r = c >> 4, sg = (c & 15) * 4;
            cp_async16(sKs[0] + (r * PW + sg) * 4, Kg + r * 64 + sg);
            cp_async16(sVs[0] + (r * PW + sg) * 4, Vg + (size_t)r * L + sg);
        }
        asm volatile("cp.async.commit_group;");
    }

    const int row0 = 16 * w + g;
    const int gq0 = q0 + row0, gq1 = gq0 + 8;

    // Q fragments in registers (scaled, tf32): reused across all k-tiles
    uint32_t qf[8][4];
    {
        const float* qr0 = Qg + (size_t)row0 * D;
        const float* qr1 = qr0 + 8 * D;
#pragma unroll
        for (int kk = 0; kk < 8; ++kk) {
            qf[kk][0] = tf32r(qr0[8 * kk + tig] * 0.125f);
            qf[kk][1] = tf32r(qr1[8 * kk + tig] * 0.125f);
            qf[kk][2] = tf32r(qr0[8 * kk + tig + 4] * 0.125f);
            qf[kk][3] = tf32r(qr1[8 * kk + tig + 4] * 0.125f);
        }
    }

    float o[8][4];
    float l0 = 0.f, l1 = 0.f;
#pragma unroll
    for (int j = 0; j < 8; ++j) { o[j][0] = o[j][1] = o[j][2] = o[j][3] = 0.f; }

    const int srcl = (lane & ~3) | (tig >> 1);     // P-conversion shuffle sources
    const int srcl2 = srcl + 2;
    const bool odd = tig & 1;

    for (int kt = 0; kt < nkt; ++kt) {
        const int k0 = kt * BK;
        const int buf = kt & 1;
        asm volatile("cp.async.wait_group 0;");
        __syncthreads();

        if (kt + 1 < nkt) {
            const int nk0 = (kt + 1) * BK;
            const int nb = buf ^ 1;
#pragma unroll
            for (int i = 0; i < 8; ++i) {
                int c = tid + i * 128;
                int r = c >> 4, sg = (c & 15) * 4;
                cp_async16(sKs[nb] + (r * PW + sg) * 4, Kg + (size_t)(nk0 + r) * 64 + sg);
                cp_async16(sVs[nb] + (r * PW + sg) * 4, Vg + (size_t)r * L + nk0 + sg);
            }
            asm volatile("cp.async.commit_group;");
        }

        // bias + mask prefetch (in flight before/during S-mma)
        float2 bv0[8], bv1[8];
#pragma unroll
        for (int j = 0; j < 8; ++j) {
            int c0 = k0 + 8 * j + 2 * tig;
            bv0[j] = *(const float2*)(Bg + (size_t)row0 * L + c0);
            bv1[j] = *(const float2*)(Bg + (size_t)(row0 + 8) * L + c0);
        }
        uint32_t mw0 = __ballot_sync(0xffffffffu, vmg[k0 + lane] != 0);
        uint32_t mw1 = __ballot_sync(0xffffffffu, vmg[k0 + 32 + lane] != 0);
        const int lim0 = gq0 - k0, lim1 = lim0 + 8;

        // ---- S = Q K^T (A from regs) ----
        float s[8][4];
#pragma unroll
        for (int j = 0; j < 8; ++j) { s[j][0] = s[j][1] = s[j][2] = s[j][3] = 0.f; }
        const float* Kb = Ks[buf];
#pragma unroll
        for (int kk = 0; kk < 8; ++kk) {
            int co = 8 * kk + 2 * tig;
#pragma unroll
            for (int j = 0; j < 8; ++j) {
                float2 b = *(const float2*)(Kb + (8 * j + g) * PW + co);
                mma8(s[j], qf[kk][0], qf[kk][1], qf[kk][2], qf[kk][3], fau(b.x), fau(b.y));
            }
        }

        // ---- bias + mask + exp (no-max) + C->A frag conversion via shuffles ----
        uint32_t p[8][4];
#pragma unroll
        for (int j = 0; j < 8; ++j) {
            int c0 = 8 * j + 2 * tig;
            uint32_t mw = (c0 < 32) ? mw0 : mw1;
            bool mk0 = (mw >> (c0 & 31)) & 1u;
            bool mk1 = (mw >> ((c0 + 1) & 31)) & 1u;
            float e0 = (mk0 && c0     <= lim0) ? __expf(s[j][0] + bv0[j].x) : 0.f;
            float e1 = (mk1 && c0 + 1 <= lim0) ? __expf(s[j][1] + bv0[j].y) : 0.f;
            float e2 = (mk0 && c0     <= lim1) ? __expf(s[j][2] + bv1[j].x) : 0.f;
            float e3 = (mk1 && c0 + 1 <= lim1) ? __expf(s[j][3] + bv1[j].y) : 0.f;
            l0 += e0 + e1;
            l1 += e2 + e3;
            uint32_t r0 = tf32r(e0), r1 = tf32r(e1), r2 = tf32r(e2), r3 = tf32r(e3);
            uint32_t u0 = __shfl_sync(0xffffffffu, r0, srcl);
            uint32_t u1 = __shfl_sync(0xffffffffu, r1, srcl);
            uint32_t u2 = __shfl_sync(0xffffffffu, r2, srcl);
            uint32_t u3 = __shfl_sync(0xffffffffu, r3, srcl);
            uint32_t v0 = __shfl_sync(0xffffffffu, r0, srcl2);
            uint32_t v1 = __shfl_sync(0xffffffffu, r1, srcl2);
            uint32_t v2 = __shfl_sync(0xffffffffu, r2, srcl2);
            uint32_t v3 = __shfl_sync(0xffffffffu, r3, srcl2);
            p[j][0] = odd ? u1 : u0;   // (row g,   col tig)
            p[j][1] = odd ? u3 : u2;   // (row g+8, col tig)
            p[j][2] = odd ? v1 : v0;   // (row g,   col tig+4)
            p[j][3] = odd ? v3 : v2;   // (row g+8, col tig+4)
        }

        // ---- O += P V (A from regs) ----
        const float* Vb = Vs[buf];
#pragma unroll
        for (int kk = 0; kk < 8; ++kk) {
            int co = 8 * kk + 2 * tig;
#pragma unroll
            for (int j = 0; j < 8; ++j) {
                float2 b = *(const float2*)(Vb + (8 * j + g) * PW + co);
                mma8(o[j], p[kk][0], p[kk][1], p[kk][2], p[kk][3], fau(b.x), fau(b.y));
            }
        }
    }

    // ---- epilogue: deferred l reduction over the quad ----
    l0 += __shfl_xor_sync(0xffffffffu, l0, 1);
    l0 += __shfl_xor_sync(0xffffffffu, l0, 2);
    l1 += __shfl_xor_sync(0xffffffffu, l1, 1);
    l1 += __shfl_xor_sync(0xffffffffu, l1, 2);

    int qm0 = qmask[(size_t)bh * L + gq0];
    int qm1 = qmask[(size_t)bh * L + gq1];
    bool fm0 = (l0 == 0.f), fm1 = (l1 == 0.f);
    float il0 = fm0 ? 0.f : 1.0f / l0;
    float il1 = fm1 ? 0.f : 1.0f / l1;
#pragma unroll
    for (int j = 0; j < 8; ++j) {
        int c = 8 * j + 2 * tig;
        float2 r0, r1;
        r0.x = !qm0 ? 0.f : (fm0 ? g_vmean[bh * D + c]     : o[j][0] * il0);
        r0.y = !qm0 ? 0.f : (fm0 ? g_vmean[bh * D + c + 1] : o[j][1] * il0);
        r1.x = !qm1 ? 0.f : (fm1 ? g_vmean[bh * D + c]     : o[j][2] * il1);
        r1.y = !qm1 ? 0.f : (fm1 ? g_vmean[bh * D + c + 1] : o[j][3] * il1);
        *(float2*)(out + ((size_t)bh * L + gq0) * D + c) = r0;
        *(float2*)(out + ((size_t)bh * L + gq1) * D + c) = r1;
    }
}

// ---------------------------------------------------------------------------
extern "C" void kernel_launch(void* const* d_in, const int* in_sizes, int n_in,
                              void* d_out, int out_size) {
    const float* Q  = (const float*)d_in[0];
    const float* K  = (const float*)d_in[1];
    const float* V  = (const float*)d_in[2];
    const int* qm   = (const int*)d_in[3];
    const int* vm   = (const int*)d_in[4];
    const float* bi = (const float*)d_in[5];
    float* out = (float*)d_out;

    constexpr int SMEM_BYTES = 4 * BK * PW * (int)sizeof(float);   // 73728
    cudaFuncSetAttribute(attn_kernel, cudaFuncAttributeMaxDynamicSharedMemorySize, SMEM_BYTES);

    kprep_kernel<<<(B * H * L * D) / 256, 256>>>(K);
    vtrans_kernel<<<dim3(L / 64, B * H), 256>>>(V);
    vmean_kernel<<<B * H, 256>>>(V);
    attn_kernel<<<dim3(NQT, B * H), THREADS, SMEM_BYTES>>>(Q, qm, vm, bi, out);
}